// round 13
// baseline (speedup 1.0000x reference)
#include <cuda_runtime.h>
#include <cuda_fp16.h>
#include <math.h>
#include <stdint.h>

// ============================================================================
// Scratch (single __device__ array, no allocations anywhere). ~230 MB.
// ============================================================================
__device__ float g_scratch[57679872];

#define OFF_LN16       0ul
#define OFF_QKV16      2097152ul
#define OFF_ATTN16     8388608ul
#define OFF_X1         10485760ul
#define OFF_X2         14680064ul
#define OFF_QDEC16     18874368ul
#define OFF_ENCKV16    20971520ul
#define OFF_H1_16      22024192ul
#define OFF_H          30412800ul
#define OFF_H16        34607104ul
#define OFF_A1_16      36704256ul
#define OFF_WT_ATTN    37228544ul
#define OFF_WT_APROJ   38801408ul
#define OFF_WT_CA      39325696ul
#define OFF_WT_CAPROJ  40898560ul
#define OFF_WT_FC      41422848ul
#define OFF_WT_MPROJ   43520000ul
#define OFF_WT_DOWN    45617152ul
#define OFF_WT_UP      45748224ul
#define OFF_ENC16      45879296ul

// ============================================================================
// Helpers
// ============================================================================
__device__ __forceinline__ float gelu_tanh(float v) {
    float u = 0.7978845608028654f * (v + 0.044715f * v * v * v);
    return 0.5f * v * (1.f + tanhf(u));
}

__device__ __forceinline__ uint32_t cvta_s(const void* p) {
    return (uint32_t)__cvta_generic_to_shared(p);
}

__device__ __forceinline__ void mma_f16(float* c, const uint32_t* a, const uint32_t* b) {
    asm volatile(
        "mma.sync.aligned.m16n8k16.row.col.f32.f16.f16.f32 "
        "{%0,%1,%2,%3}, {%4,%5,%6,%7}, {%8,%9}, {%0,%1,%2,%3};"
        : "+f"(c[0]), "+f"(c[1]), "+f"(c[2]), "+f"(c[3])
        : "r"(a[0]), "r"(a[1]), "r"(a[2]), "r"(a[3]), "r"(b[0]), "r"(b[1]));
}

__device__ __forceinline__ void ldsm_x4(uint32_t* r, uint32_t addr) {
    asm volatile("ldmatrix.sync.aligned.m8n8.x4.shared.b16 {%0,%1,%2,%3}, [%4];"
        : "=r"(r[0]), "=r"(r[1]), "=r"(r[2]), "=r"(r[3]) : "r"(addr));
}

__device__ __forceinline__ void ldsm_x4_t(uint32_t* r, uint32_t addr) {
    asm volatile("ldmatrix.sync.aligned.m8n8.x4.trans.shared.b16 {%0,%1,%2,%3}, [%4];"
        : "=r"(r[0]), "=r"(r[1]), "=r"(r[2]), "=r"(r[3]) : "r"(addr));
}

__device__ __forceinline__ void cp_async16(uint32_t dst, const void* src, unsigned sz) {
    asm volatile("cp.async.cg.shared.global [%0], [%1], 16, %2;"
        :: "r"(dst), "l"(src), "r"(sz));
}
__device__ __forceinline__ void cp_commit() { asm volatile("cp.async.commit_group;"); }
template <int N>
__device__ __forceinline__ void cp_wait() { asm volatile("cp.async.wait_group %0;" :: "n"(N)); }

// ============================================================================
// LayerNorm: one block per row, C=1024, 256 threads, float4 per thread.
// ============================================================================
__global__ void ln_kernel(const float* __restrict__ x, const float* __restrict__ g,
                          const float* __restrict__ b, __half* __restrict__ out) {
    const int C = 1024;
    int row = blockIdx.x;
    int i4 = threadIdx.x * 4;
    const float* xr = x + (size_t)row * C;
    float4 v = *(const float4*)(xr + i4);
    float s  = v.x + v.y + v.z + v.w;
    float ss = v.x * v.x + v.y * v.y + v.z * v.z + v.w * v.w;
    #pragma unroll
    for (int o = 16; o; o >>= 1) {
        s  += __shfl_xor_sync(0xffffffffu, s, o);
        ss += __shfl_xor_sync(0xffffffffu, ss, o);
    }
    __shared__ float rs[8], rss[8];
    __shared__ float sh_m, sh_r;
    int w = threadIdx.x >> 5;
    if ((threadIdx.x & 31) == 0) { rs[w] = s; rss[w] = ss; }
    __syncthreads();
    if (threadIdx.x == 0) {
        float S = 0.f, SS = 0.f;
        #pragma unroll
        for (int i = 0; i < 8; i++) { S += rs[i]; SS += rss[i]; }
        float m = S / C;
        float vv = SS / C - m * m;
        sh_m = m; sh_r = rsqrtf(vv + 1e-5f);
    }
    __syncthreads();
    float m = sh_m, rst = sh_r;
    float4 g4 = *(const float4*)(g + i4);
    float4 b4 = *(const float4*)(b + i4);
    half2 h01 = make_half2(__float2half_rn((v.x - m) * rst * g4.x + b4.x),
                           __float2half_rn((v.y - m) * rst * g4.y + b4.y));
    half2 h23 = make_half2(__float2half_rn((v.z - m) * rst * g4.z + b4.z),
                           __float2half_rn((v.w - m) * rst * g4.w + b4.w));
    half2* op = (half2*)(out + (size_t)row * C + i4);
    op[0] = h01; op[1] = h23;
}

// ============================================================================
// Weight transpose to fp16: Wt[n][k] = h(W[k][n]). K,N mult of 32.
// ============================================================================
__global__ void transpose_h(const float* __restrict__ W, __half* __restrict__ Wt,
                            int K, int N) {
    __shared__ float t[32][33];
    int k0 = blockIdx.x * 32, n0 = blockIdx.y * 32;
    int tx = threadIdx.x & 31, ty = threadIdx.x >> 5;
    #pragma unroll
    for (int i = 0; i < 32; i += 8)
        t[ty + i][tx] = W[(size_t)(k0 + ty + i) * N + n0 + tx];
    __syncthreads();
    #pragma unroll
    for (int i = 0; i < 32; i += 8)
        Wt[(size_t)(n0 + ty + i) * K + k0 + tx] = __float2half_rn(t[tx][ty + i]);
}

__global__ void round_copy_h(const float* __restrict__ in, __half* __restrict__ out, int n4) {
    int i = blockIdx.x * 256 + threadIdx.x;
    if (i < n4) {
        float4 v = *(const float4*)(in + i * 4);
        half2* op = (half2*)(out + i * 4);
        op[0] = make_half2(__float2half_rn(v.x), __float2half_rn(v.y));
        op[1] = make_half2(__float2half_rn(v.z), __float2half_rn(v.w));
    }
}

// ============================================================================
// FP16 NT GEMM — round-11 mainloop, pipeline deepened 4 -> 5 stages (ONLY
// change this round). BM=128, BN=128, BK=32 halves, ldmatrix b16, m16n8k16.
// 256 threads, 8 warps (2m x 4n), warp tile 64x32, 2 CTAs/SM (204.8KB/SM).
// ============================================================================
#define HKD 40
#define G1STG 5
#define HSTAGE_HALFS (128 * HKD)
#define GEMM_SMEM (2 * G1STG * HSTAGE_HALFS * 2)   // 102,400 B

__global__ void __launch_bounds__(256, 2) h16_gemm(
    const __half* __restrict__ A, int lda,
    const __half* __restrict__ Bw, int ldb,
    const float* __restrict__ bias,
    const float* __restrict__ res1, const float* __restrict__ res2,
    float* __restrict__ Cf, __half* __restrict__ Ch, int ldc,
    int M, int K, int dogelu) {
    extern __shared__ __half hsm[];
    __half* As = hsm;
    __half* Bs = hsm + G1STG * HSTAGE_HALFS;

    int tid = threadIdx.x, lane = tid & 31, warp = tid >> 5;
    int wm = warp & 1, wn = warp >> 1;
    int g = lane >> 2, t4 = lane & 3;
    int bm = blockIdx.y * 128, bn = blockIdx.x * 128;

    int crow = tid >> 1;
    int cch = (tid & 1) * 2;
    const __half* Agp = A + (size_t)(bm + crow) * lda + cch * 8;
    const __half* Bgp = Bw + (size_t)(bn + crow) * ldb + cch * 8;
    unsigned aok = (bm + crow) < M ? 16u : 0u;
    uint32_t sa = cvta_s(As) + (crow * HKD + cch * 8) * 2;
    uint32_t sb = cvta_s(Bs) + (crow * HKD + cch * 8) * 2;
    const uint32_t stB = HSTAGE_HALFS * 2;

#define H_ISSUE(t_) do { \
        int slot_ = (t_) % G1STG; \
        size_t ko_ = (size_t)((t_) << 5); \
        cp_async16(sa + slot_ * stB,       Agp + ko_,      aok); \
        cp_async16(sa + slot_ * stB + 16,  Agp + ko_ + 8,  aok); \
        cp_async16(sb + slot_ * stB,       Bgp + ko_,      16u); \
        cp_async16(sb + slot_ * stB + 16,  Bgp + ko_ + 8,  16u); \
    } while (0)

    uint32_t a_ro = lane & 15, a_ko = (lane >> 4) * 8;
    uint32_t b_ro = (lane & 7) + ((lane >> 4) & 1) * 8, b_ko = ((lane >> 3) & 1) * 8;
    uint32_t abase = cvta_s(As) + ((wm * 64 + a_ro) * HKD + a_ko) * 2;
    uint32_t bbase = cvta_s(Bs) + ((wn * 32 + b_ro) * HKD + b_ko) * 2;

    float acc[4][4][4];
    #pragma unroll
    for (int i = 0; i < 4; i++)
        #pragma unroll
        for (int j = 0; j < 4; j++)
            #pragma unroll
            for (int l = 0; l < 4; l++) acc[i][j][l] = 0.f;

    int nk = K >> 5;
    #pragma unroll
    for (int s = 0; s < G1STG - 1; s++) { H_ISSUE(s); cp_commit(); }

    for (int t = 0; t < nk; t++) {
        cp_wait<G1STG - 2>();
        __syncthreads();
        if (t + G1STG - 1 < nk) H_ISSUE(t + G1STG - 1);
        cp_commit();

        int slot = t % G1STG;
        uint32_t aS = abase + slot * stB;
        uint32_t bS = bbase + slot * stB;
        #pragma unroll
        for (int ks = 0; ks < 32; ks += 16) {
            uint32_t af[4][4], bf[2][4];
            #pragma unroll
            for (int mt = 0; mt < 4; mt++)
                ldsm_x4(af[mt], aS + (mt * 16 * HKD + ks) * 2);
            #pragma unroll
            for (int np = 0; np < 2; np++)
                ldsm_x4(bf[np], bS + (np * 16 * HKD + ks) * 2);
            #pragma unroll
            for (int mt = 0; mt < 4; mt++)
                #pragma unroll
                for (int nt = 0; nt < 4; nt++)
                    mma_f16(acc[mt][nt], af[mt], &bf[nt >> 1][(nt & 1) * 2]);
        }
    }
#undef H_ISSUE

    #pragma unroll
    for (int mt = 0; mt < 4; mt++) {
        int row0 = bm + wm * 64 + mt * 16 + g;
        int row1 = row0 + 8;
        #pragma unroll
        for (int nt = 0; nt < 4; nt++) {
            int col = bn + wn * 32 + nt * 8 + 2 * t4;
            float bx = bias[col], by = bias[col + 1];
            float v00 = acc[mt][nt][0] + bx, v01 = acc[mt][nt][1] + by;
            float v10 = acc[mt][nt][2] + bx, v11 = acc[mt][nt][3] + by;
            if (row0 < M) {
                size_t i0 = (size_t)row0 * ldc + col;
                if (res1) { float2 r = *(const float2*)(res1 + i0); v00 += r.x; v01 += r.y; }
                if (res2) { float2 r = *(const float2*)(res2 + i0); v00 += r.x; v01 += r.y; }
                if (dogelu) { v00 = gelu_tanh(v00); v01 = gelu_tanh(v01); }
                if (Cf) *(float2*)(Cf + i0) = make_float2(v00, v01);
                if (Ch) *(half2*)(Ch + i0) =
                    make_half2(__float2half_rn(v00), __float2half_rn(v01));
            }
            if (row1 < M) {
                size_t i1 = (size_t)row1 * ldc + col;
                if (res1) { float2 r = *(const float2*)(res1 + i1); v10 += r.x; v11 += r.y; }
                if (res2) { float2 r = *(const float2*)(res2 + i1); v10 += r.x; v11 += r.y; }
                if (dogelu) { v10 = gelu_tanh(v10); v11 = gelu_tanh(v11); }
                if (Cf) *(float2*)(Cf + i1) = make_float2(v10, v11);
                if (Ch) *(half2*)(Ch + i1) =
                    make_half2(__float2half_rn(v10), __float2half_rn(v11));
            }
        }
    }
}

// ============================================================================
// Standalone BM=64 GEMM for the small-N down-projection (round-11 proven,
// kept at 4 stages — untouched).
// ============================================================================
#define G2STG 4
#define A64STG (64 * HKD)
#define GEMM64_SMEM ((A64STG + HSTAGE_HALFS) * G2STG * 2)

__global__ void __launch_bounds__(256, 2) h16_gemm_bm64(
    const __half* __restrict__ A, int lda,
    const __half* __restrict__ Bw, int ldb,
    const float* __restrict__ bias,
    float* __restrict__ Cf, __half* __restrict__ Ch, int ldc,
    int M, int K, int dogelu) {
    extern __shared__ __half hsm[];
    __half* As = hsm;
    __half* Bs = hsm + G2STG * A64STG;

    int tid = threadIdx.x, lane = tid & 31, warp = tid >> 5;
    int wn = warp;
    int g = lane >> 2, t4 = lane & 3;
    int bm = blockIdx.y * 64, bn = blockIdx.x * 128;

    int arow = tid >> 2;
    int ao = (tid & 3) * 8;
    const __half* Agp = A + (size_t)(bm + arow) * lda + ao;
    unsigned aok = (bm + arow) < M ? 16u : 0u;
    uint32_t sa = cvta_s(As) + (arow * HKD + ao) * 2;
    int brow = tid >> 1;
    int bo = (tid & 1) * 16;
    const __half* Bgp = Bw + (size_t)(bn + brow) * ldb + bo;
    uint32_t sb = cvta_s(Bs) + (brow * HKD + bo) * 2;
    const uint32_t aStB = A64STG * 2, bStB = HSTAGE_HALFS * 2;

#define H64_ISSUE(t_) do { \
        int slot_ = (t_) & (G2STG - 1); \
        size_t ko_ = (size_t)((t_) << 5); \
        cp_async16(sa + slot_ * aStB,      Agp + ko_,     aok); \
        cp_async16(sb + slot_ * bStB,      Bgp + ko_,     16u); \
        cp_async16(sb + slot_ * bStB + 16, Bgp + ko_ + 8, 16u); \
    } while (0)

    uint32_t a_ro = lane & 15, a_ko = (lane >> 4) * 8;
    uint32_t b_ro = (lane & 7) + ((lane >> 4) & 1) * 8, b_ko = ((lane >> 3) & 1) * 8;
    uint32_t abase = cvta_s(As) + ((a_ro) * HKD + a_ko) * 2;
    uint32_t bbase = cvta_s(Bs) + ((wn * 16 + b_ro) * HKD + b_ko) * 2;

    float acc[4][2][4];
    #pragma unroll
    for (int i = 0; i < 4; i++)
        #pragma unroll
        for (int j = 0; j < 2; j++)
            #pragma unroll
            for (int l = 0; l < 4; l++) acc[i][j][l] = 0.f;

    int nk = K >> 5;
    #pragma unroll
    for (int s = 0; s < G2STG - 1; s++) { H64_ISSUE(s); cp_commit(); }

    for (int t = 0; t < nk; t++) {
        cp_wait<G2STG - 2>();
        __syncthreads();
        if (t + G2STG - 1 < nk) H64_ISSUE(t + G2STG - 1);
        cp_commit();

        int slot = t & (G2STG - 1);
        uint32_t aS = abase + slot * aStB;
        uint32_t bS = bbase + slot * bStB;
        #pragma unroll
        for (int ks = 0; ks < 32; ks += 16) {
            uint32_t af[4][4], bf[4];
            #pragma unroll
            for (int mt = 0; mt < 4; mt++)
                ldsm_x4(af[mt], aS + (mt * 16 * HKD + ks) * 2);
            ldsm_x4(bf, bS + ks * 2);
            #pragma unroll
            for (int mt = 0; mt < 4; mt++) {
                mma_f16(acc[mt][0], af[mt], bf);
                mma_f16(acc[mt][1], af[mt], bf + 2);
            }
        }
    }
#undef H64_ISSUE

    #pragma unroll
    for (int mt = 0; mt < 4; mt++) {
        int row0 = bm + mt * 16 + g;
        int row1 = row0 + 8;
        #pragma unroll
        for (int nt = 0; nt < 2; nt++) {
            int col = bn + wn * 16 + nt * 8 + 2 * t4;
            float bx = bias[col], by = bias[col + 1];
            float v00 = acc[mt][nt][0] + bx, v01 = acc[mt][nt][1] + by;
            float v10 = acc[mt][nt][2] + bx, v11 = acc[mt][nt][3] + by;
            if (row0 < M) {
                size_t i0 = (size_t)row0 * ldc + col;
                if (dogelu) { v00 = gelu_tanh(v00); v01 = gelu_tanh(v01); }
                if (Cf) *(float2*)(Cf + i0) = make_float2(v00, v01);
                if (Ch) *(half2*)(Ch + i0) =
                    make_half2(__float2half_rn(v00), __float2half_rn(v01));
            }
            if (row1 < M) {
                size_t i1 = (size_t)row1 * ldc + col;
                if (dogelu) { v10 = gelu_tanh(v10); v11 = gelu_tanh(v11); }
                if (Cf) *(float2*)(Cf + i1) = make_float2(v10, v11);
                if (Ch) *(half2*)(Ch + i1) =
                    make_half2(__float2half_rn(v10), __float2half_rn(v11));
            }
        }
    }
}

// ============================================================================
// FP16 tensor-core flash attention (round-9/11 proven — reverted from R12),
// D=64, 64 Q rows/block, 4 warps. V row-major + trans-ldmatrix PV.
// ============================================================================
#define ATS 72

template <bool CAUSAL>
__global__ void __launch_bounds__(128) attn_h16(
    const __half* __restrict__ Qb, long qts, long qbs,
    const __half* __restrict__ Kb, long kts, long kbs,
    const __half* __restrict__ Vb,
    __half* __restrict__ O, int Tq, int Tk, float scale) {
    __shared__ __half Qs[64 * ATS];
    __shared__ __half Ks[64 * ATS];
    __shared__ __half Vs[64 * ATS];
    __shared__ __half Ps[64 * ATS];

    int b = blockIdx.z, h = blockIdx.y, qt = blockIdx.x;
    int tid = threadIdx.x, lane = tid & 31, wq = tid >> 5;
    int g = lane >> 2, t4 = lane & 3;

    const __half* Qp = Qb + (size_t)b * qbs + h * 64;
    const __half* Kp = Kb + (size_t)b * kbs + h * 64;
    const __half* Vp = Vb + (size_t)b * kbs + h * 64;

    #pragma unroll
    for (int i = 0; i < 4; i++) {
        int idx = tid + i * 128;
        int r = idx >> 3, c8 = (idx & 7) * 8;
        uint4 v = *(const uint4*)(Qp + (size_t)(qt * 64 + r) * qts + c8);
        *(uint4*)&Qs[r * ATS + c8] = v;
    }

    uint32_t a_ro = lane & 15, a_ko = (lane >> 4) * 8;
    uint32_t b_ro = (lane & 7) + ((lane >> 4) & 1) * 8, b_ko = ((lane >> 3) & 1) * 8;
    uint32_t qs_b = cvta_s(Qs) + ((wq * 16 + a_ro) * ATS + a_ko) * 2;
    uint32_t ks_b = cvta_s(Ks) + (b_ro * ATS + b_ko) * 2;
    uint32_t vt_b = cvta_s(Vs) + ((lane & 15) * ATS + (lane >> 4) * 8) * 2;
    uint32_t ps_b = cvta_s(Ps) + ((wq * 16 + a_ro) * ATS + a_ko) * 2;

    float m0 = -1e30f, m1 = -1e30f, l0 = 0.f, l1 = 0.f;
    float acc_o[8][4];
    #pragma unroll
    for (int i = 0; i < 8; i++)
        #pragma unroll
        for (int j = 0; j < 4; j++) acc_o[i][j] = 0.f;

    int q0 = qt * 64 + wq * 16 + g, q1 = q0 + 8;
    int nkt = CAUSAL ? (qt + 1) : (Tk + 63) >> 6;

    for (int kt = 0; kt < nkt; kt++) {
        __syncthreads();
        #pragma unroll
        for (int i = 0; i < 4; i++) {
            int idx = tid + i * 128;
            int rr = idx >> 3, c8 = (idx & 7) * 8;
            int t = kt * 64 + rr;
            uint4 kv, vv;
            if (t < Tk) {
                kv = *(const uint4*)(Kp + (size_t)t * kts + c8);
                vv = *(const uint4*)(Vp + (size_t)t * kts + c8);
            } else {
                kv = make_uint4(0, 0, 0, 0);
                vv = kv;
            }
            *(uint4*)&Ks[rr * ATS + c8] = kv;
            *(uint4*)&Vs[rr * ATS + c8] = vv;
        }
        __syncthreads();

        float s[8][4];
        #pragma unroll
        for (int i = 0; i < 8; i++)
            #pragma unroll
            for (int j = 0; j < 4; j++) s[i][j] = 0.f;
        #pragma unroll
        for (int ks = 0; ks < 64; ks += 16) {
            uint32_t a[4];
            ldsm_x4(a, qs_b + ks * 2);
            #pragma unroll
            for (int np = 0; np < 4; np++) {
                uint32_t bf[4];
                ldsm_x4(bf, ks_b + (np * 16 * ATS + ks) * 2);
                mma_f16(s[np * 2], a, bf);
                mma_f16(s[np * 2 + 1], a, bf + 2);
            }
        }

        float rm0 = -1e30f, rm1 = -1e30f;
        #pragma unroll
        for (int nt = 0; nt < 8; nt++) {
            int k0g = kt * 64 + nt * 8 + 2 * t4;
            int k1g = k0g + 1;
            bool c00 = (k0g < Tk) && (!CAUSAL || k0g <= q0);
            bool c01 = (k1g < Tk) && (!CAUSAL || k1g <= q0);
            bool c10 = (k0g < Tk) && (!CAUSAL || k0g <= q1);
            bool c11 = (k1g < Tk) && (!CAUSAL || k1g <= q1);
            s[nt][0] = c00 ? s[nt][0] * scale : -1e30f;
            s[nt][1] = c01 ? s[nt][1] * scale : -1e30f;
            s[nt][2] = c10 ? s[nt][2] * scale : -1e30f;
            s[nt][3] = c11 ? s[nt][3] * scale : -1e30f;
            rm0 = fmaxf(rm0, fmaxf(s[nt][0], s[nt][1]));
            rm1 = fmaxf(rm1, fmaxf(s[nt][2], s[nt][3]));
        }
        rm0 = fmaxf(rm0, __shfl_xor_sync(0xffffffffu, rm0, 1));
        rm0 = fmaxf(rm0, __shfl_xor_sync(0xffffffffu, rm0, 2));
        rm1 = fmaxf(rm1, __shfl_xor_sync(0xffffffffu, rm1, 1));
        rm1 = fmaxf(rm1, __shfl_xor_sync(0xffffffffu, rm1, 2));

        float mn0 = fmaxf(m0, rm0), mn1 = fmaxf(m1, rm1);
        float al0 = __expf(m0 - mn0), al1 = __expf(m1 - mn1);
        float ps0 = 0.f, ps1 = 0.f;
        int pr0 = (wq * 16 + g) * ATS, pr1 = (wq * 16 + g + 8) * ATS;
        #pragma unroll
        for (int nt = 0; nt < 8; nt++) {
            __half p00 = __float2half_rn(__expf(s[nt][0] - mn0));
            __half p01 = __float2half_rn(__expf(s[nt][1] - mn0));
            __half p10 = __float2half_rn(__expf(s[nt][2] - mn1));
            __half p11 = __float2half_rn(__expf(s[nt][3] - mn1));
            ps0 += __half2float(p00) + __half2float(p01);
            ps1 += __half2float(p10) + __half2float(p11);
            int c = nt * 8 + 2 * t4;
            *(half2*)&Ps[pr0 + c] = make_half2(p00, p01);
            *(half2*)&Ps[pr1 + c] = make_half2(p10, p11);
        }
        ps0 += __shfl_xor_sync(0xffffffffu, ps0, 1);
        ps0 += __shfl_xor_sync(0xffffffffu, ps0, 2);
        ps1 += __shfl_xor_sync(0xffffffffu, ps1, 1);
        ps1 += __shfl_xor_sync(0xffffffffu, ps1, 2);
        l0 = l0 * al0 + ps0;
        l1 = l1 * al1 + ps1;
        m0 = mn0; m1 = mn1;
        #pragma unroll
        for (int nt = 0; nt < 8; nt++) {
            acc_o[nt][0] *= al0; acc_o[nt][1] *= al0;
            acc_o[nt][2] *= al1; acc_o[nt][3] *= al1;
        }
        __syncwarp();

        #pragma unroll
        for (int ks = 0; ks < 64; ks += 16) {
            uint32_t a[4];
            ldsm_x4(a, ps_b + ks * 2);
            #pragma unroll
            for (int np = 0; np < 4; np++) {
                uint32_t bf[4];
                ldsm_x4_t(bf, vt_b + (ks * ATS + np * 16) * 2);
                mma_f16(acc_o[np * 2], a, bf);
                mma_f16(acc_o[np * 2 + 1], a, bf + 2);
            }
        }
    }

    float i0 = 1.f / l0, i1 = 1.f / l1;
    #pragma unroll
    for (int nt = 0; nt < 8; nt++) {
        int c = h * 64 + nt * 8 + 2 * t4;
        __half* p0 = O + (size_t)(b * Tq + q0) * 1024 + c;
        __half* p1 = O + (size_t)(b * Tq + q1) * 1024 + c;
        *(half2*)p0 = make_half2(__float2half_rn(acc_o[nt][0] * i0),
                                 __float2half_rn(acc_o[nt][1] * i0));
        *(half2*)p1 = make_half2(__float2half_rn(acc_o[nt][2] * i1),
                                 __float2half_rn(acc_o[nt][3] * i1));
    }
}

// ============================================================================
// Launch — main chain on legacy stream; prep + enc_kv GEMM on side stream.
// ============================================================================
extern "C" void kernel_launch(void* const* d_in, const int* in_sizes, int n_in,
                              void* d_out, int out_size) {
    (void)in_sizes; (void)n_in; (void)out_size;
    const float* x        = (const float*)d_in[0];
    const float* enc      = (const float*)d_in[1];
    const float* ln1_g    = (const float*)d_in[3];
    const float* ln1_b    = (const float*)d_in[4];
    const float* ln2_g    = (const float*)d_in[5];
    const float* ln2_b    = (const float*)d_in[6];
    const float* ln3_g    = (const float*)d_in[7];
    const float* ln3_b    = (const float*)d_in[8];
    const float* attn_w   = (const float*)d_in[9];
    const float* attn_b   = (const float*)d_in[10];
    const float* aproj_w  = (const float*)d_in[11];
    const float* aproj_b  = (const float*)d_in[12];
    const float* ca_w     = (const float*)d_in[13];
    const float* ca_b     = (const float*)d_in[14];
    const float* caproj_w = (const float*)d_in[15];
    const float* caproj_b = (const float*)d_in[16];
    const float* fc_w     = (const float*)d_in[17];
    const float* fc_b     = (const float*)d_in[18];
    const float* mproj_w  = (const float*)d_in[19];
    const float* mproj_b  = (const float*)d_in[20];
    const float* down_w   = (const float*)d_in[21];
    const float* down_b   = (const float*)d_in[22];
    const float* up_w     = (const float*)d_in[23];
    const float* up_b     = (const float*)d_in[24];
    float* out = (float*)d_out;

    float* base = nullptr;
    cudaGetSymbolAddress((void**)&base, g_scratch);
    __half* ln16     = (__half*)(base + OFF_LN16);
    __half* qkv16    = (__half*)(base + OFF_QKV16);
    __half* attn16   = (__half*)(base + OFF_ATTN16);
    float*  x1       = base + OFF_X1;
    float*  x2       = base + OFF_X2;
    __half* qdec16   = (__half*)(base + OFF_QDEC16);
    __half* enckv16  = (__half*)(base + OFF_ENCKV16);
    __half* h1_16    = (__half*)(base + OFF_H1_16);
    float*  hbuf     = base + OFF_H;
    __half* h16      = (__half*)(base + OFF_H16);
    __half* a1_16    = (__half*)(base + OFF_A1_16);
    __half* wt_attn  = (__half*)(base + OFF_WT_ATTN);
    __half* wt_aproj = (__half*)(base + OFF_WT_APROJ);
    __half* wt_ca    = (__half*)(base + OFF_WT_CA);
    __half* wt_caproj= (__half*)(base + OFF_WT_CAPROJ);
    __half* wt_fc    = (__half*)(base + OFF_WT_FC);
    __half* wt_mproj = (__half*)(base + OFF_WT_MPROJ);
    __half* wt_down  = (__half*)(base + OFF_WT_DOWN);
    __half* wt_up    = (__half*)(base + OFF_WT_UP);
    __half* enc16    = (__half*)(base + OFF_ENC16);

    const int B = 4, T = 1024, Te = 257, C = 1024, H = 16;
    const int M  = B * T;   // 4096
    const int Me = B * Te;  // 1028
    const float scale = 0.125f;

    cudaFuncSetAttribute(h16_gemm, cudaFuncAttributeMaxDynamicSharedMemorySize, GEMM_SMEM);
    cudaFuncSetAttribute(h16_gemm_bm64, cudaFuncAttributeMaxDynamicSharedMemorySize, GEMM64_SMEM);

    cudaStream_t s2;
    cudaStreamCreateWithFlags(&s2, cudaStreamNonBlocking);
    cudaEvent_t e0, e1, e2, e3;
    cudaEventCreateWithFlags(&e0, cudaEventDisableTiming);
    cudaEventCreateWithFlags(&e1, cudaEventDisableTiming);
    cudaEventCreateWithFlags(&e2, cudaEventDisableTiming);
    cudaEventCreateWithFlags(&e3, cudaEventDisableTiming);

    // ---- fork: prep on s2 ----
    cudaEventRecord(e0, 0);
    cudaStreamWaitEvent(s2, e0, 0);

    transpose_h<<<dim3(C / 32, 3072 / 32), 256, 0, s2>>>(attn_w, wt_attn, C, 3072);
    cudaEventRecord(e1, s2);   // qkv GEMM gate
    transpose_h<<<dim3(C / 32, 1024 / 32), 256, 0, s2>>>(aproj_w,  wt_aproj,  C, 1024);
    transpose_h<<<dim3(C / 32, 3072 / 32), 256, 0, s2>>>(ca_w,     wt_ca,     C, 3072);
    transpose_h<<<dim3(C / 32, 1024 / 32), 256, 0, s2>>>(caproj_w, wt_caproj, C, 1024);
    transpose_h<<<dim3(C / 32, 4096 / 32), 256, 0, s2>>>(fc_w,     wt_fc,     C, 4096);
    transpose_h<<<dim3(4096 / 32, 1024 / 32), 256, 0, s2>>>(mproj_w, wt_mproj, 4096, 1024);
    transpose_h<<<dim3(C / 32, 256 / 32), 256, 0, s2>>>(down_w,   wt_down,   C, 256);
    transpose_h<<<dim3(256 / 32, 1024 / 32), 256, 0, s2>>>(up_w,   wt_up,     256, 1024);
    round_copy_h<<<(Me * C / 4 + 255) / 256, 256, 0, s2>>>(enc, enc16, Me * C / 4);
    cudaEventRecord(e2, s2);   // all-weights gate
    // 7. enc_kv = enc @ ca_w[:, 1024:] + ca_b[1024:]  [1028, 2048] fp16 — on s2
    h16_gemm<<<dim3(2048 / 128, (Me + 127) / 128), 256, GEMM_SMEM, s2>>>(
        enc16, C, wt_ca + (size_t)1024 * C, C, ca_b + 1024, nullptr, nullptr,
        nullptr, enckv16, 2048, Me, C, 0);
    cudaEventRecord(e3, s2);   // enc_kv gate

    // ---- main chain on legacy stream ----
    // 1. ln1 = LN(x) -> fp16
    ln_kernel<<<M, 256>>>(x, ln1_g, ln1_b, ln16);
    cudaStreamWaitEvent(0, e1, 0);
    // 2. qkv = ln1 @ attn_w + attn_b   [4096, 3072] fp16
    h16_gemm<<<dim3(3072 / 128, M / 128), 256, GEMM_SMEM>>>(
        ln16, C, wt_attn, C, attn_b, nullptr, nullptr, nullptr, qkv16, 3072, M, C, 0);
    // 3. self-attention (causal) -> fp16
    attn_h16<true><<<dim3(T / 64, H, B), 128>>>(
        qkv16,        (long)3072, (long)T * 3072,
        qkv16 + 1024, (long)3072, (long)T * 3072,
        qkv16 + 2048, attn16, T, T, scale);
    cudaStreamWaitEvent(0, e2, 0);
    // 4. x1 = x + attn @ aproj_w + aproj_b   (fp32)
    h16_gemm<<<dim3(1024 / 128, M / 128), 256, GEMM_SMEM>>>(
        attn16, C, wt_aproj, C, aproj_b, x, nullptr, x1, nullptr, C, M, C, 0);
    // 5. ln2 = LN(x1) -> fp16
    ln_kernel<<<M, 256>>>(x1, ln2_g, ln2_b, ln16);
    // 6. q_dec = ln2 @ ca_w[:, :1024] + ca_b[:1024]  fp16
    h16_gemm<<<dim3(1024 / 128, M / 128), 256, GEMM_SMEM>>>(
        ln16, C, wt_ca, C, ca_b, nullptr, nullptr, nullptr, qdec16, C, M, C, 0);
    cudaStreamWaitEvent(0, e3, 0);
    // 8. cross-attention (non-causal, Tk=257) -> fp16
    attn_h16<false><<<dim3(T / 64, H, B), 128>>>(
        qdec16,  (long)1024, (long)T * 1024,
        enckv16, (long)2048, (long)Te * 2048,
        enckv16 + 1024, attn16, T, Te, scale);
    // 9. x2 = x1 + ca_out @ caproj_w + caproj_b   (fp32)
    h16_gemm<<<dim3(1024 / 128, M / 128), 256, GEMM_SMEM>>>(
        attn16, C, wt_caproj, C, caproj_b, x1, nullptr, x2, nullptr, C, M, C, 0);
    // 10. ln3 = LN(x2) -> fp16
    ln_kernel<<<M, 256>>>(x2, ln3_g, ln3_b, ln16);
    // 11. h1 = gelu(ln3 @ fc_w + fc_b)   [4096, 4096] fp16
    h16_gemm<<<dim3(4096 / 128, M / 128), 256, GEMM_SMEM>>>(
        ln16, C, wt_fc, C, fc_b, nullptr, nullptr, nullptr, h1_16, 4096, M, C, 1);
    // 12. h = h1 @ mproj_w + mproj_b   [4096, 1024]  fp32 + fp16
    h16_gemm<<<dim3(1024 / 128, M / 128), 256, GEMM_SMEM>>>(
        h1_16, 4096, wt_mproj, 4096, mproj_b, nullptr, nullptr, hbuf, h16, C, M, 4096, 0);
    // 13. a1 = gelu(h @ down_w + down_b)   [4096, 256] fp16 — BM=64 standalone
    h16_gemm_bm64<<<dim3(256 / 128, M / 64), 256, GEMM64_SMEM>>>(
        h16, C, wt_down, C, down_b, nullptr, a1_16, 256, M, C, 1);
    // 14. out = x2 + h + a1 @ up_w + up_b   (fp32)
    h16_gemm<<<dim3(1024 / 128, M / 128), 256, GEMM_SMEM>>>(
        a1_16, 256, wt_up, 256, up_b, hbuf, x2, out, nullptr, C, M, 256, 0);
}

// round 14
// speedup vs baseline: 1.0976x; 1.0976x over previous
#include <cuda_runtime.h>
#include <cuda_fp16.h>
#include <math.h>
#include <stdint.h>

// ============================================================================
// Scratch (single __device__ array, no allocations anywhere). ~230 MB.
// ============================================================================
__device__ float g_scratch[57679872];

#define OFF_LN16       0ul
#define OFF_QKV16      2097152ul
#define OFF_ATTN16     8388608ul
#define OFF_X1         10485760ul
#define OFF_X2         14680064ul
#define OFF_QDEC16     18874368ul
#define OFF_ENCKV16    20971520ul
#define OFF_H1_16      22024192ul
#define OFF_H          30412800ul
#define OFF_H16        34607104ul
#define OFF_A1_16      36704256ul
#define OFF_WT_ATTN    37228544ul
#define OFF_WT_APROJ   38801408ul
#define OFF_WT_CA      39325696ul
#define OFF_WT_CAPROJ  40898560ul
#define OFF_WT_FC      41422848ul
#define OFF_WT_MPROJ   43520000ul
#define OFF_WT_DOWN    45617152ul
#define OFF_WT_UP      45748224ul
#define OFF_ENC16      45879296ul

// ============================================================================
// Helpers
// ============================================================================
__device__ __forceinline__ float gelu_tanh(float v) {
    float u = 0.7978845608028654f * (v + 0.044715f * v * v * v);
    return 0.5f * v * (1.f + tanhf(u));
}

__device__ __forceinline__ uint32_t cvta_s(const void* p) {
    return (uint32_t)__cvta_generic_to_shared(p);
}

__device__ __forceinline__ void mma_f16(float* c, const uint32_t* a, const uint32_t* b) {
    asm volatile(
        "mma.sync.aligned.m16n8k16.row.col.f32.f16.f16.f32 "
        "{%0,%1,%2,%3}, {%4,%5,%6,%7}, {%8,%9}, {%0,%1,%2,%3};"
        : "+f"(c[0]), "+f"(c[1]), "+f"(c[2]), "+f"(c[3])
        : "r"(a[0]), "r"(a[1]), "r"(a[2]), "r"(a[3]), "r"(b[0]), "r"(b[1]));
}

__device__ __forceinline__ void ldsm_x4(uint32_t* r, uint32_t addr) {
    asm volatile("ldmatrix.sync.aligned.m8n8.x4.shared.b16 {%0,%1,%2,%3}, [%4];"
        : "=r"(r[0]), "=r"(r[1]), "=r"(r[2]), "=r"(r[3]) : "r"(addr));
}

__device__ __forceinline__ void ldsm_x4_t(uint32_t* r, uint32_t addr) {
    asm volatile("ldmatrix.sync.aligned.m8n8.x4.trans.shared.b16 {%0,%1,%2,%3}, [%4];"
        : "=r"(r[0]), "=r"(r[1]), "=r"(r[2]), "=r"(r[3]) : "r"(addr));
}

__device__ __forceinline__ void cp_async16(uint32_t dst, const void* src, unsigned sz) {
    asm volatile("cp.async.cg.shared.global [%0], [%1], 16, %2;"
        :: "r"(dst), "l"(src), "r"(sz));
}
__device__ __forceinline__ void cp_commit() { asm volatile("cp.async.commit_group;"); }
template <int N>
__device__ __forceinline__ void cp_wait() { asm volatile("cp.async.wait_group %0;" :: "n"(N)); }

// ============================================================================
// LayerNorm: one block per row, C=1024, 256 threads, float4 per thread.
// ============================================================================
__global__ void ln_kernel(const float* __restrict__ x, const float* __restrict__ g,
                          const float* __restrict__ b, __half* __restrict__ out) {
    const int C = 1024;
    int row = blockIdx.x;
    int i4 = threadIdx.x * 4;
    const float* xr = x + (size_t)row * C;
    float4 v = *(const float4*)(xr + i4);
    float s  = v.x + v.y + v.z + v.w;
    float ss = v.x * v.x + v.y * v.y + v.z * v.z + v.w * v.w;
    #pragma unroll
    for (int o = 16; o; o >>= 1) {
        s  += __shfl_xor_sync(0xffffffffu, s, o);
        ss += __shfl_xor_sync(0xffffffffu, ss, o);
    }
    __shared__ float rs[8], rss[8];
    __shared__ float sh_m, sh_r;
    int w = threadIdx.x >> 5;
    if ((threadIdx.x & 31) == 0) { rs[w] = s; rss[w] = ss; }
    __syncthreads();
    if (threadIdx.x == 0) {
        float S = 0.f, SS = 0.f;
        #pragma unroll
        for (int i = 0; i < 8; i++) { S += rs[i]; SS += rss[i]; }
        float m = S / C;
        float vv = SS / C - m * m;
        sh_m = m; sh_r = rsqrtf(vv + 1e-5f);
    }
    __syncthreads();
    float m = sh_m, rst = sh_r;
    float4 g4 = *(const float4*)(g + i4);
    float4 b4 = *(const float4*)(b + i4);
    half2 h01 = make_half2(__float2half_rn((v.x - m) * rst * g4.x + b4.x),
                           __float2half_rn((v.y - m) * rst * g4.y + b4.y));
    half2 h23 = make_half2(__float2half_rn((v.z - m) * rst * g4.z + b4.z),
                           __float2half_rn((v.w - m) * rst * g4.w + b4.w));
    half2* op = (half2*)(out + (size_t)row * C + i4);
    op[0] = h01; op[1] = h23;
}

// ============================================================================
// Weight transpose to fp16: Wt[n][k] = h(W[k][n]). K,N mult of 32.
// ============================================================================
__global__ void transpose_h(const float* __restrict__ W, __half* __restrict__ Wt,
                            int K, int N) {
    __shared__ float t[32][33];
    int k0 = blockIdx.x * 32, n0 = blockIdx.y * 32;
    int tx = threadIdx.x & 31, ty = threadIdx.x >> 5;
    #pragma unroll
    for (int i = 0; i < 32; i += 8)
        t[ty + i][tx] = W[(size_t)(k0 + ty + i) * N + n0 + tx];
    __syncthreads();
    #pragma unroll
    for (int i = 0; i < 32; i += 8)
        Wt[(size_t)(n0 + ty + i) * K + k0 + tx] = __float2half_rn(t[tx][ty + i]);
}

__global__ void round_copy_h(const float* __restrict__ in, __half* __restrict__ out, int n4) {
    int i = blockIdx.x * 256 + threadIdx.x;
    if (i < n4) {
        float4 v = *(const float4*)(in + i * 4);
        half2* op = (half2*)(out + i * 4);
        op[0] = make_half2(__float2half_rn(v.x), __float2half_rn(v.y));
        op[1] = make_half2(__float2half_rn(v.z), __float2half_rn(v.w));
    }
}

// ============================================================================
// FP16 NT GEMM (round-5/7/9/11 proven): C[M,N] = A[M,K] @ Wt[N,K]^T + bias
// (+res1)(+res2), opt GELU. Outputs Cf (fp32) and/or Ch (fp16).
// BM=128, BN=128, BK=32 halves, 4-stage cp.async, ldmatrix b16, m16n8k16.
// 256 threads, 8 warps (2m x 4n), warp tile 64x32, 2 CTAs/SM.
// ============================================================================
#define HKD 40
#define HSTG 4
#define HSTAGE_HALFS (128 * HKD)
#define GEMM_SMEM (2 * HSTG * HSTAGE_HALFS * 2)

__global__ void __launch_bounds__(256, 2) h16_gemm(
    const __half* __restrict__ A, int lda,
    const __half* __restrict__ Bw, int ldb,
    const float* __restrict__ bias,
    const float* __restrict__ res1, const float* __restrict__ res2,
    float* __restrict__ Cf, __half* __restrict__ Ch, int ldc,
    int M, int K, int dogelu) {
    extern __shared__ __half hsm[];
    __half* As = hsm;
    __half* Bs = hsm + HSTG * HSTAGE_HALFS;

    int tid = threadIdx.x, lane = tid & 31, warp = tid >> 5;
    int wm = warp & 1, wn = warp >> 1;
    int g = lane >> 2, t4 = lane & 3;
    int bm = blockIdx.y * 128, bn = blockIdx.x * 128;

    int crow = tid >> 1;
    int cch = (tid & 1) * 2;
    const __half* Agp = A + (size_t)(bm + crow) * lda + cch * 8;
    const __half* Bgp = Bw + (size_t)(bn + crow) * ldb + cch * 8;
    unsigned aok = (bm + crow) < M ? 16u : 0u;
    uint32_t sa = cvta_s(As) + (crow * HKD + cch * 8) * 2;
    uint32_t sb = cvta_s(Bs) + (crow * HKD + cch * 8) * 2;
    const uint32_t stB = HSTAGE_HALFS * 2;

#define H_ISSUE(t_) do { \
        int slot_ = (t_) & (HSTG - 1); \
        size_t ko_ = (size_t)((t_) << 5); \
        cp_async16(sa + slot_ * stB,       Agp + ko_,      aok); \
        cp_async16(sa + slot_ * stB + 16,  Agp + ko_ + 8,  aok); \
        cp_async16(sb + slot_ * stB,       Bgp + ko_,      16u); \
        cp_async16(sb + slot_ * stB + 16,  Bgp + ko_ + 8,  16u); \
    } while (0)

    uint32_t a_ro = lane & 15, a_ko = (lane >> 4) * 8;
    uint32_t b_ro = (lane & 7) + ((lane >> 4) & 1) * 8, b_ko = ((lane >> 3) & 1) * 8;
    uint32_t abase = cvta_s(As) + ((wm * 64 + a_ro) * HKD + a_ko) * 2;
    uint32_t bbase = cvta_s(Bs) + ((wn * 32 + b_ro) * HKD + b_ko) * 2;

    float acc[4][4][4];
    #pragma unroll
    for (int i = 0; i < 4; i++)
        #pragma unroll
        for (int j = 0; j < 4; j++)
            #pragma unroll
            for (int l = 0; l < 4; l++) acc[i][j][l] = 0.f;

    int nk = K >> 5;
    #pragma unroll
    for (int s = 0; s < HSTG - 1; s++) { H_ISSUE(s); cp_commit(); }

    for (int t = 0; t < nk; t++) {
        cp_wait<HSTG - 2>();
        __syncthreads();
        if (t + HSTG - 1 < nk) H_ISSUE(t + HSTG - 1);
        cp_commit();

        int slot = t & (HSTG - 1);
        uint32_t aS = abase + slot * stB;
        uint32_t bS = bbase + slot * stB;
        #pragma unroll
        for (int ks = 0; ks < 32; ks += 16) {
            uint32_t af[4][4], bf[2][4];
            #pragma unroll
            for (int mt = 0; mt < 4; mt++)
                ldsm_x4(af[mt], aS + (mt * 16 * HKD + ks) * 2);
            #pragma unroll
            for (int np = 0; np < 2; np++)
                ldsm_x4(bf[np], bS + (np * 16 * HKD + ks) * 2);
            #pragma unroll
            for (int mt = 0; mt < 4; mt++)
                #pragma unroll
                for (int nt = 0; nt < 4; nt++)
                    mma_f16(acc[mt][nt], af[mt], &bf[nt >> 1][(nt & 1) * 2]);
        }
    }
#undef H_ISSUE

    #pragma unroll
    for (int mt = 0; mt < 4; mt++) {
        int row0 = bm + wm * 64 + mt * 16 + g;
        int row1 = row0 + 8;
        #pragma unroll
        for (int nt = 0; nt < 4; nt++) {
            int col = bn + wn * 32 + nt * 8 + 2 * t4;
            float bx = bias[col], by = bias[col + 1];
            float v00 = acc[mt][nt][0] + bx, v01 = acc[mt][nt][1] + by;
            float v10 = acc[mt][nt][2] + bx, v11 = acc[mt][nt][3] + by;
            if (row0 < M) {
                size_t i0 = (size_t)row0 * ldc + col;
                if (res1) { float2 r = *(const float2*)(res1 + i0); v00 += r.x; v01 += r.y; }
                if (res2) { float2 r = *(const float2*)(res2 + i0); v00 += r.x; v01 += r.y; }
                if (dogelu) { v00 = gelu_tanh(v00); v01 = gelu_tanh(v01); }
                if (Cf) *(float2*)(Cf + i0) = make_float2(v00, v01);
                if (Ch) *(half2*)(Ch + i0) =
                    make_half2(__float2half_rn(v00), __float2half_rn(v01));
            }
            if (row1 < M) {
                size_t i1 = (size_t)row1 * ldc + col;
                if (res1) { float2 r = *(const float2*)(res1 + i1); v10 += r.x; v11 += r.y; }
                if (res2) { float2 r = *(const float2*)(res2 + i1); v10 += r.x; v11 += r.y; }
                if (dogelu) { v10 = gelu_tanh(v10); v11 = gelu_tanh(v11); }
                if (Cf) *(float2*)(Cf + i1) = make_float2(v10, v11);
                if (Ch) *(half2*)(Ch + i1) =
                    make_half2(__float2half_rn(v10), __float2half_rn(v11));
            }
        }
    }
}

// ============================================================================
// Standalone BM=64 GEMM for the small-N down-projection (round-11 proven).
// ============================================================================
#define A64STG (64 * HKD)
#define GEMM64_SMEM ((A64STG + HSTAGE_HALFS) * HSTG * 2)

__global__ void __launch_bounds__(256, 2) h16_gemm_bm64(
    const __half* __restrict__ A, int lda,
    const __half* __restrict__ Bw, int ldb,
    const float* __restrict__ bias,
    float* __restrict__ Cf, __half* __restrict__ Ch, int ldc,
    int M, int K, int dogelu) {
    extern __shared__ __half hsm[];
    __half* As = hsm;
    __half* Bs = hsm + HSTG * A64STG;

    int tid = threadIdx.x, lane = tid & 31, warp = tid >> 5;
    int wn = warp;
    int g = lane >> 2, t4 = lane & 3;
    int bm = blockIdx.y * 64, bn = blockIdx.x * 128;

    int arow = tid >> 2;
    int ao = (tid & 3) * 8;
    const __half* Agp = A + (size_t)(bm + arow) * lda + ao;
    unsigned aok = (bm + arow) < M ? 16u : 0u;
    uint32_t sa = cvta_s(As) + (arow * HKD + ao) * 2;
    int brow = tid >> 1;
    int bo = (tid & 1) * 16;
    const __half* Bgp = Bw + (size_t)(bn + brow) * ldb + bo;
    uint32_t sb = cvta_s(Bs) + (brow * HKD + bo) * 2;
    const uint32_t aStB = A64STG * 2, bStB = HSTAGE_HALFS * 2;

#define H64_ISSUE(t_) do { \
        int slot_ = (t_) & (HSTG - 1); \
        size_t ko_ = (size_t)((t_) << 5); \
        cp_async16(sa + slot_ * aStB,      Agp + ko_,     aok); \
        cp_async16(sb + slot_ * bStB,      Bgp + ko_,     16u); \
        cp_async16(sb + slot_ * bStB + 16, Bgp + ko_ + 8, 16u); \
    } while (0)

    uint32_t a_ro = lane & 15, a_ko = (lane >> 4) * 8;
    uint32_t b_ro = (lane & 7) + ((lane >> 4) & 1) * 8, b_ko = ((lane >> 3) & 1) * 8;
    uint32_t abase = cvta_s(As) + ((a_ro) * HKD + a_ko) * 2;
    uint32_t bbase = cvta_s(Bs) + ((wn * 16 + b_ro) * HKD + b_ko) * 2;

    float acc[4][2][4];
    #pragma unroll
    for (int i = 0; i < 4; i++)
        #pragma unroll
        for (int j = 0; j < 2; j++)
            #pragma unroll
            for (int l = 0; l < 4; l++) acc[i][j][l] = 0.f;

    int nk = K >> 5;
    #pragma unroll
    for (int s = 0; s < HSTG - 1; s++) { H64_ISSUE(s); cp_commit(); }

    for (int t = 0; t < nk; t++) {
        cp_wait<HSTG - 2>();
        __syncthreads();
        if (t + HSTG - 1 < nk) H64_ISSUE(t + HSTG - 1);
        cp_commit();

        int slot = t & (HSTG - 1);
        uint32_t aS = abase + slot * aStB;
        uint32_t bS = bbase + slot * bStB;
        #pragma unroll
        for (int ks = 0; ks < 32; ks += 16) {
            uint32_t af[4][4], bf[4];
            #pragma unroll
            for (int mt = 0; mt < 4; mt++)
                ldsm_x4(af[mt], aS + (mt * 16 * HKD + ks) * 2);
            ldsm_x4(bf, bS + ks * 2);
            #pragma unroll
            for (int mt = 0; mt < 4; mt++) {
                mma_f16(acc[mt][0], af[mt], bf);
                mma_f16(acc[mt][1], af[mt], bf + 2);
            }
        }
    }
#undef H64_ISSUE

    #pragma unroll
    for (int mt = 0; mt < 4; mt++) {
        int row0 = bm + mt * 16 + g;
        int row1 = row0 + 8;
        #pragma unroll
        for (int nt = 0; nt < 2; nt++) {
            int col = bn + wn * 16 + nt * 8 + 2 * t4;
            float bx = bias[col], by = bias[col + 1];
            float v00 = acc[mt][nt][0] + bx, v01 = acc[mt][nt][1] + by;
            float v10 = acc[mt][nt][2] + bx, v11 = acc[mt][nt][3] + by;
            if (row0 < M) {
                size_t i0 = (size_t)row0 * ldc + col;
                if (dogelu) { v00 = gelu_tanh(v00); v01 = gelu_tanh(v01); }
                if (Cf) *(float2*)(Cf + i0) = make_float2(v00, v01);
                if (Ch) *(half2*)(Ch + i0) =
                    make_half2(__float2half_rn(v00), __float2half_rn(v01));
            }
            if (row1 < M) {
                size_t i1 = (size_t)row1 * ldc + col;
                if (dogelu) { v10 = gelu_tanh(v10); v11 = gelu_tanh(v11); }
                if (Cf) *(float2*)(Cf + i1) = make_float2(v10, v11);
                if (Ch) *(half2*)(Ch + i1) =
                    make_half2(__float2half_rn(v10), __float2half_rn(v11));
            }
        }
    }
}

// ============================================================================
// FP16 tensor-core flash attention (round-9/11 proven), D=64, 64 Q rows/block,
// 4 warps. V row-major [ktok][d] + trans-ldmatrix PV.
// ============================================================================
#define ATS 72

template <bool CAUSAL>
__global__ void __launch_bounds__(128) attn_h16(
    const __half* __restrict__ Qb, long qts, long qbs,
    const __half* __restrict__ Kb, long kts, long kbs,
    const __half* __restrict__ Vb,
    __half* __restrict__ O, int Tq, int Tk, float scale) {
    __shared__ __half Qs[64 * ATS];
    __shared__ __half Ks[64 * ATS];
    __shared__ __half Vs[64 * ATS];
    __shared__ __half Ps[64 * ATS];

    int b = blockIdx.z, h = blockIdx.y, qt = blockIdx.x;
    int tid = threadIdx.x, lane = tid & 31, wq = tid >> 5;
    int g = lane >> 2, t4 = lane & 3;

    const __half* Qp = Qb + (size_t)b * qbs + h * 64;
    const __half* Kp = Kb + (size_t)b * kbs + h * 64;
    const __half* Vp = Vb + (size_t)b * kbs + h * 64;

    #pragma unroll
    for (int i = 0; i < 4; i++) {
        int idx = tid + i * 128;
        int r = idx >> 3, c8 = (idx & 7) * 8;
        uint4 v = *(const uint4*)(Qp + (size_t)(qt * 64 + r) * qts + c8);
        *(uint4*)&Qs[r * ATS + c8] = v;
    }

    uint32_t a_ro = lane & 15, a_ko = (lane >> 4) * 8;
    uint32_t b_ro = (lane & 7) + ((lane >> 4) & 1) * 8, b_ko = ((lane >> 3) & 1) * 8;
    uint32_t qs_b = cvta_s(Qs) + ((wq * 16 + a_ro) * ATS + a_ko) * 2;
    uint32_t ks_b = cvta_s(Ks) + (b_ro * ATS + b_ko) * 2;
    uint32_t vt_b = cvta_s(Vs) + ((lane & 15) * ATS + (lane >> 4) * 8) * 2;
    uint32_t ps_b = cvta_s(Ps) + ((wq * 16 + a_ro) * ATS + a_ko) * 2;

    float m0 = -1e30f, m1 = -1e30f, l0 = 0.f, l1 = 0.f;
    float acc_o[8][4];
    #pragma unroll
    for (int i = 0; i < 8; i++)
        #pragma unroll
        for (int j = 0; j < 4; j++) acc_o[i][j] = 0.f;

    int q0 = qt * 64 + wq * 16 + g, q1 = q0 + 8;
    int nkt = CAUSAL ? (qt + 1) : (Tk + 63) >> 6;

    for (int kt = 0; kt < nkt; kt++) {
        __syncthreads();
        #pragma unroll
        for (int i = 0; i < 4; i++) {
            int idx = tid + i * 128;
            int rr = idx >> 3, c8 = (idx & 7) * 8;
            int t = kt * 64 + rr;
            uint4 kv, vv;
            if (t < Tk) {
                kv = *(const uint4*)(Kp + (size_t)t * kts + c8);
                vv = *(const uint4*)(Vp + (size_t)t * kts + c8);
            } else {
                kv = make_uint4(0, 0, 0, 0);
                vv = kv;
            }
            *(uint4*)&Ks[rr * ATS + c8] = kv;
            *(uint4*)&Vs[rr * ATS + c8] = vv;
        }
        __syncthreads();

        float s[8][4];
        #pragma unroll
        for (int i = 0; i < 8; i++)
            #pragma unroll
            for (int j = 0; j < 4; j++) s[i][j] = 0.f;
        #pragma unroll
        for (int ks = 0; ks < 64; ks += 16) {
            uint32_t a[4];
            ldsm_x4(a, qs_b + ks * 2);
            #pragma unroll
            for (int np = 0; np < 4; np++) {
                uint32_t bf[4];
                ldsm_x4(bf, ks_b + (np * 16 * ATS + ks) * 2);
                mma_f16(s[np * 2], a, bf);
                mma_f16(s[np * 2 + 1], a, bf + 2);
            }
        }

        float rm0 = -1e30f, rm1 = -1e30f;
        #pragma unroll
        for (int nt = 0; nt < 8; nt++) {
            int k0g = kt * 64 + nt * 8 + 2 * t4;
            int k1g = k0g + 1;
            bool c00 = (k0g < Tk) && (!CAUSAL || k0g <= q0);
            bool c01 = (k1g < Tk) && (!CAUSAL || k1g <= q0);
            bool c10 = (k0g < Tk) && (!CAUSAL || k0g <= q1);
            bool c11 = (k1g < Tk) && (!CAUSAL || k1g <= q1);
            s[nt][0] = c00 ? s[nt][0] * scale : -1e30f;
            s[nt][1] = c01 ? s[nt][1] * scale : -1e30f;
            s[nt][2] = c10 ? s[nt][2] * scale : -1e30f;
            s[nt][3] = c11 ? s[nt][3] * scale : -1e30f;
            rm0 = fmaxf(rm0, fmaxf(s[nt][0], s[nt][1]));
            rm1 = fmaxf(rm1, fmaxf(s[nt][2], s[nt][3]));
        }
        rm0 = fmaxf(rm0, __shfl_xor_sync(0xffffffffu, rm0, 1));
        rm0 = fmaxf(rm0, __shfl_xor_sync(0xffffffffu, rm0, 2));
        rm1 = fmaxf(rm1, __shfl_xor_sync(0xffffffffu, rm1, 1));
        rm1 = fmaxf(rm1, __shfl_xor_sync(0xffffffffu, rm1, 2));

        float mn0 = fmaxf(m0, rm0), mn1 = fmaxf(m1, rm1);
        float al0 = __expf(m0 - mn0), al1 = __expf(m1 - mn1);
        float ps0 = 0.f, ps1 = 0.f;
        int pr0 = (wq * 16 + g) * ATS, pr1 = (wq * 16 + g + 8) * ATS;
        #pragma unroll
        for (int nt = 0; nt < 8; nt++) {
            __half p00 = __float2half_rn(__expf(s[nt][0] - mn0));
            __half p01 = __float2half_rn(__expf(s[nt][1] - mn0));
            __half p10 = __float2half_rn(__expf(s[nt][2] - mn1));
            __half p11 = __float2half_rn(__expf(s[nt][3] - mn1));
            ps0 += __half2float(p00) + __half2float(p01);
            ps1 += __half2float(p10) + __half2float(p11);
            int c = nt * 8 + 2 * t4;
            *(half2*)&Ps[pr0 + c] = make_half2(p00, p01);
            *(half2*)&Ps[pr1 + c] = make_half2(p10, p11);
        }
        ps0 += __shfl_xor_sync(0xffffffffu, ps0, 1);
        ps0 += __shfl_xor_sync(0xffffffffu, ps0, 2);
        ps1 += __shfl_xor_sync(0xffffffffu, ps1, 1);
        ps1 += __shfl_xor_sync(0xffffffffu, ps1, 2);
        l0 = l0 * al0 + ps0;
        l1 = l1 * al1 + ps1;
        m0 = mn0; m1 = mn1;
        #pragma unroll
        for (int nt = 0; nt < 8; nt++) {
            acc_o[nt][0] *= al0; acc_o[nt][1] *= al0;
            acc_o[nt][2] *= al1; acc_o[nt][3] *= al1;
        }
        __syncwarp();

        #pragma unroll
        for (int ks = 0; ks < 64; ks += 16) {
            uint32_t a[4];
            ldsm_x4(a, ps_b + ks * 2);
            #pragma unroll
            for (int np = 0; np < 4; np++) {
                uint32_t bf[4];
                ldsm_x4_t(bf, vt_b + (ks * ATS + np * 16) * 2);
                mma_f16(acc_o[np * 2], a, bf);
                mma_f16(acc_o[np * 2 + 1], a, bf + 2);
            }
        }
    }

    float i0 = 1.f / l0, i1 = 1.f / l1;
    #pragma unroll
    for (int nt = 0; nt < 8; nt++) {
        int c = h * 64 + nt * 8 + 2 * t4;
        __half* p0 = O + (size_t)(b * Tq + q0) * 1024 + c;
        __half* p1 = O + (size_t)(b * Tq + q1) * 1024 + c;
        *(half2*)p0 = make_half2(__float2half_rn(acc_o[nt][0] * i0),
                                 __float2half_rn(acc_o[nt][1] * i0));
        *(half2*)p1 = make_half2(__float2half_rn(acc_o[nt][2] * i1),
                                 __float2half_rn(acc_o[nt][3] * i1));
    }
}

// ============================================================================
// Launch — main chain on legacy stream; prep + enc_kv GEMM on side stream.
// ============================================================================
extern "C" void kernel_launch(void* const* d_in, const int* in_sizes, int n_in,
                              void* d_out, int out_size) {
    (void)in_sizes; (void)n_in; (void)out_size;
    const float* x        = (const float*)d_in[0];
    const float* enc      = (const float*)d_in[1];
    const float* ln1_g    = (const float*)d_in[3];
    const float* ln1_b    = (const float*)d_in[4];
    const float* ln2_g    = (const float*)d_in[5];
    const float* ln2_b    = (const float*)d_in[6];
    const float* ln3_g    = (const float*)d_in[7];
    const float* ln3_b    = (const float*)d_in[8];
    const float* attn_w   = (const float*)d_in[9];
    const float* attn_b   = (const float*)d_in[10];
    const float* aproj_w  = (const float*)d_in[11];
    const float* aproj_b  = (const float*)d_in[12];
    const float* ca_w     = (const float*)d_in[13];
    const float* ca_b     = (const float*)d_in[14];
    const float* caproj_w = (const float*)d_in[15];
    const float* caproj_b = (const float*)d_in[16];
    const float* fc_w     = (const float*)d_in[17];
    const float* fc_b     = (const float*)d_in[18];
    const float* mproj_w  = (const float*)d_in[19];
    const float* mproj_b  = (const float*)d_in[20];
    const float* down_w   = (const float*)d_in[21];
    const float* down_b   = (const float*)d_in[22];
    const float* up_w     = (const float*)d_in[23];
    const float* up_b     = (const float*)d_in[24];
    float* out = (float*)d_out;

    float* base = nullptr;
    cudaGetSymbolAddress((void**)&base, g_scratch);
    __half* ln16     = (__half*)(base + OFF_LN16);
    __half* qkv16    = (__half*)(base + OFF_QKV16);
    __half* attn16   = (__half*)(base + OFF_ATTN16);
    float*  x1       = base + OFF_X1;
    float*  x2       = base + OFF_X2;
    __half* qdec16   = (__half*)(base + OFF_QDEC16);
    __half* enckv16  = (__half*)(base + OFF_ENCKV16);
    __half* h1_16    = (__half*)(base + OFF_H1_16);
    float*  hbuf     = base + OFF_H;
    __half* h16      = (__half*)(base + OFF_H16);
    __half* a1_16    = (__half*)(base + OFF_A1_16);
    __half* wt_attn  = (__half*)(base + OFF_WT_ATTN);
    __half* wt_aproj = (__half*)(base + OFF_WT_APROJ);
    __half* wt_ca    = (__half*)(base + OFF_WT_CA);
    __half* wt_caproj= (__half*)(base + OFF_WT_CAPROJ);
    __half* wt_fc    = (__half*)(base + OFF_WT_FC);
    __half* wt_mproj = (__half*)(base + OFF_WT_MPROJ);
    __half* wt_down  = (__half*)(base + OFF_WT_DOWN);
    __half* wt_up    = (__half*)(base + OFF_WT_UP);
    __half* enc16    = (__half*)(base + OFF_ENC16);

    const int B = 4, T = 1024, Te = 257, C = 1024, H = 16;
    const int M  = B * T;   // 4096
    const int Me = B * Te;  // 1028
    const float scale = 0.125f;

    cudaFuncSetAttribute(h16_gemm, cudaFuncAttributeMaxDynamicSharedMemorySize, GEMM_SMEM);
    cudaFuncSetAttribute(h16_gemm_bm64, cudaFuncAttributeMaxDynamicSharedMemorySize, GEMM64_SMEM);

    cudaStream_t s2;
    cudaStreamCreateWithFlags(&s2, cudaStreamNonBlocking);
    cudaEvent_t e0, e1, e2, e3;
    cudaEventCreateWithFlags(&e0, cudaEventDisableTiming);
    cudaEventCreateWithFlags(&e1, cudaEventDisableTiming);
    cudaEventCreateWithFlags(&e2, cudaEventDisableTiming);
    cudaEventCreateWithFlags(&e3, cudaEventDisableTiming);

    // ---- fork: prep on s2 ----
    cudaEventRecord(e0, 0);
    cudaStreamWaitEvent(s2, e0, 0);

    transpose_h<<<dim3(C / 32, 3072 / 32), 256, 0, s2>>>(attn_w, wt_attn, C, 3072);
    cudaEventRecord(e1, s2);   // qkv GEMM gate
    transpose_h<<<dim3(C / 32, 1024 / 32), 256, 0, s2>>>(aproj_w,  wt_aproj,  C, 1024);
    transpose_h<<<dim3(C / 32, 3072 / 32), 256, 0, s2>>>(ca_w,     wt_ca,     C, 3072);
    transpose_h<<<dim3(C / 32, 1024 / 32), 256, 0, s2>>>(caproj_w, wt_caproj, C, 1024);
    transpose_h<<<dim3(C / 32, 4096 / 32), 256, 0, s2>>>(fc_w,     wt_fc,     C, 4096);
    transpose_h<<<dim3(4096 / 32, 1024 / 32), 256, 0, s2>>>(mproj_w, wt_mproj, 4096, 1024);
    transpose_h<<<dim3(C / 32, 256 / 32), 256, 0, s2>>>(down_w,   wt_down,   C, 256);
    transpose_h<<<dim3(256 / 32, 1024 / 32), 256, 0, s2>>>(up_w,   wt_up,     256, 1024);
    round_copy_h<<<(Me * C / 4 + 255) / 256, 256, 0, s2>>>(enc, enc16, Me * C / 4);
    cudaEventRecord(e2, s2);   // all-weights gate
    // 7. enc_kv = enc @ ca_w[:, 1024:] + ca_b[1024:]  [1028, 2048] fp16 — on s2
    h16_gemm<<<dim3(2048 / 128, (Me + 127) / 128), 256, GEMM_SMEM, s2>>>(
        enc16, C, wt_ca + (size_t)1024 * C, C, ca_b + 1024, nullptr, nullptr,
        nullptr, enckv16, 2048, Me, C, 0);
    cudaEventRecord(e3, s2);   // enc_kv gate

    // ---- main chain on legacy stream ----
    // 1. ln1 = LN(x) -> fp16
    ln_kernel<<<M, 256>>>(x, ln1_g, ln1_b, ln16);
    cudaStreamWaitEvent(0, e1, 0);
    // 2. qkv = ln1 @ attn_w + attn_b   [4096, 3072] fp16
    h16_gemm<<<dim3(3072 / 128, M / 128), 256, GEMM_SMEM>>>(
        ln16, C, wt_attn, C, attn_b, nullptr, nullptr, nullptr, qkv16, 3072, M, C, 0);
    // 3. self-attention (causal) -> fp16
    attn_h16<true><<<dim3(T / 64, H, B), 128>>>(
        qkv16,        (long)3072, (long)T * 3072,
        qkv16 + 1024, (long)3072, (long)T * 3072,
        qkv16 + 2048, attn16, T, T, scale);
    cudaStreamWaitEvent(0, e2, 0);
    // 4. x1 = x + attn @ aproj_w + aproj_b   (fp32)
    h16_gemm<<<dim3(1024 / 128, M / 128), 256, GEMM_SMEM>>>(
        attn16, C, wt_aproj, C, aproj_b, x, nullptr, x1, nullptr, C, M, C, 0);
    // 5. ln2 = LN(x1) -> fp16
    ln_kernel<<<M, 256>>>(x1, ln2_g, ln2_b, ln16);
    // 6. q_dec = ln2 @ ca_w[:, :1024] + ca_b[:1024]  fp16
    h16_gemm<<<dim3(1024 / 128, M / 128), 256, GEMM_SMEM>>>(
        ln16, C, wt_ca, C, ca_b, nullptr, nullptr, nullptr, qdec16, C, M, C, 0);
    cudaStreamWaitEvent(0, e3, 0);
    // 8. cross-attention (non-causal, Tk=257) -> fp16
    attn_h16<false><<<dim3(T / 64, H, B), 128>>>(
        qdec16,  (long)1024, (long)T * 1024,
        enckv16, (long)2048, (long)Te * 2048,
        enckv16 + 1024, attn16, T, Te, scale);
    // 9. x2 = x1 + ca_out @ caproj_w + caproj_b   (fp32)
    h16_gemm<<<dim3(1024 / 128, M / 128), 256, GEMM_SMEM>>>(
        attn16, C, wt_caproj, C, caproj_b, x1, nullptr, x2, nullptr, C, M, C, 0);
    // 10. ln3 = LN(x2) -> fp16
    ln_kernel<<<M, 256>>>(x2, ln3_g, ln3_b, ln16);
    // 11. h1 = gelu(ln3 @ fc_w + fc_b)   [4096, 4096] fp16
    h16_gemm<<<dim3(4096 / 128, M / 128), 256, GEMM_SMEM>>>(
        ln16, C, wt_fc, C, fc_b, nullptr, nullptr, nullptr, h1_16, 4096, M, C, 1);
    // 12. h = h1 @ mproj_w + mproj_b   [4096, 1024]  fp32 + fp16
    h16_gemm<<<dim3(1024 / 128, M / 128), 256, GEMM_SMEM>>>(
        h1_16, 4096, wt_mproj, 4096, mproj_b, nullptr, nullptr, hbuf, h16, C, M, 4096, 0);
    // 13. a1 = gelu(h @ down_w + down_b)   [4096, 256] fp16 — BM=64 standalone
    h16_gemm_bm64<<<dim3(256 / 128, M / 64), 256, GEMM64_SMEM>>>(
        h16, C, wt_down, C, down_b, nullptr, a1_16, 256, M, C, 1);
    // 14. out = x2 + h + a1 @ up_w + up_b   (fp32)
    h16_gemm<<<dim3(1024 / 128, M / 128), 256, GEMM_SMEM>>>(
        a1_16, 256, wt_up, 256, up_b, hbuf, x2, out, nullptr, C, M, 256, 0);
}